// round 8
// baseline (speedup 1.0000x reference)
#include <cuda_runtime.h>
#include <cuda_bf16.h>
#include <cstdint>

#define NN 100000
#define EE 1600000
#define HH 128
#define GG 500

// ---------------- scratch (static __device__ globals; no allocation) ----------------
__device__ float g_bufA[NN * HH];     // ping
__device__ float g_bufB[NN * HH];     // pong (xw)
__device__ float g_deg[NN];           // deg -> dinv (in place)
__device__ int   g_cnt[NN];           // histogram / fill counter
__device__ int   g_rowptr[NN + 1];
__device__ int2  g_epack[EE];         // {row, norm-bits} per CSR-ordered edge
__device__ int   g_part[128];         // scan partials (98 used)
__device__ int   g_aIsBatch;          // input-disambiguation flag

// ---------------- z/batch detector ----------------
__global__ void k_detect(const int* __restrict__ a) {
    int i = threadIdx.x;                       // 512 threads
    int v  = a[i];
    int vp = (i > 0) ? a[i - 1] : 0;
    int ok = (v >= 0) && (v < GG) && (v >= vp);
    int all = __syncthreads_and(ok);
    if (i == 0) g_aIsBatch = all;
}

// ---------------- degree ----------------
__global__ void k_init() {
    int i = blockIdx.x * blockDim.x + threadIdx.x;
    if (i < NN) { g_deg[i] = 1.0f; g_cnt[i] = 0; }   // self-loop weight 1
}

__global__ void k_count(const int* __restrict__ ei, const float* __restrict__ w) {
    int e = blockIdx.x * blockDim.x + threadIdx.x;
    if (e < EE) {
        int c = ei[EE + e];
        atomicAdd(&g_deg[c], w[e]);
        atomicAdd(&g_cnt[c], 1);
    }
}

// ---------------- CSR build (scan1 also computes dinv in place) ----------------
__global__ void k_scan1() {   // blocks of 1024 over g_cnt
    __shared__ int s[1024];
    int tid = threadIdx.x;
    int i = blockIdx.x * 1024 + tid;
    if (i < NN) { float d = g_deg[i]; g_deg[i] = (d > 0.f) ? rsqrtf(d) : 0.f; }
    int v = (i < NN) ? g_cnt[i] : 0;
    s[tid] = v; __syncthreads();
    #pragma unroll
    for (int off = 1; off < 1024; off <<= 1) {
        int t = (tid >= off) ? s[tid - off] : 0;
        __syncthreads();
        s[tid] += t; __syncthreads();
    }
    if (i < NN) g_rowptr[i] = s[tid] - v;         // exclusive within block
    if (tid == 1023) g_part[blockIdx.x] = s[1023];
}

__global__ void k_scan2(int nblocks) {   // one 128-thread block, parallel scan
    __shared__ int s[128];
    int tid = threadIdx.x;
    int v = (tid < nblocks) ? g_part[tid] : 0;
    s[tid] = v; __syncthreads();
    #pragma unroll
    for (int off = 1; off < 128; off <<= 1) {
        int t = (tid >= off) ? s[tid - off] : 0;
        __syncthreads();
        s[tid] += t; __syncthreads();
    }
    if (tid < nblocks) g_part[tid] = s[tid] - v;  // exclusive
    if (tid == 127) g_rowptr[NN] = s[127];
}

__global__ void k_scan3() {
    int i = blockIdx.x * blockDim.x + threadIdx.x;
    if (i < NN) { g_rowptr[i] += g_part[i >> 10]; g_cnt[i] = 0; }
}

// fused: CSR fill + norm computation + epack write (one edge pass)
__global__ void k_fill(const int* __restrict__ ei, const float* __restrict__ w) {
    int e = blockIdx.x * blockDim.x + threadIdx.x;
    if (e < EE) {
        int r = ei[e];
        int c = ei[EE + e];
        float nm = g_deg[r] * w[e] * g_deg[c];    // g_deg holds dinv
        int pos = g_rowptr[c] + atomicAdd(&g_cnt[c], 1);
        g_epack[pos] = make_int2(r, __float_as_int(nm));
    }
}

// ---------------- 3xTF32 tensor-core GEMM: Y[M,128] = X[M,128] @ W[128,128] ----------------
// BM=128, 256 threads (8 warps). Warp tile 32x64 = 2 m16 x 8 n8, K=128 (16 k8 steps).
// W split (hi/lo tf32) precomputed once per block into smem; X split in registers.
// Layer 0 fuses the embedding lookup: X row r = ztab[z[r]].
__device__ __forceinline__ void tf32_split(float x, uint32_t& hi, uint32_t& lo) {
    asm("cvt.rna.tf32.f32 %0, %1;" : "=r"(hi) : "f"(x));
    float r = x - __uint_as_float(hi);
    asm("cvt.rna.tf32.f32 %0, %1;" : "=r"(lo) : "f"(r));
}

__global__ void __launch_bounds__(256, 1)
k_gemm(const float* __restrict__ X, const float* __restrict__ W, float* __restrict__ Y,
       const int* __restrict__ za, const int* __restrict__ zb,
       const float* __restrict__ ztab, int useEmbed) {
    extern __shared__ float sm[];
    float* Xs  = sm;                      // [128][132]
    float* Whi = sm + 128 * 132;          // [128][136]
    float* Wlo = Whi + 128 * 136;         // [128][136]
    int tid = threadIdx.x;
    int row0 = blockIdx.x * 128;

    // load W, split into hi/lo tf32 (vector stores)
    const float4* Wv = (const float4*)W;
    #pragma unroll
    for (int i = 0; i < 16; ++i) {
        int idx = tid + i * 256;            // 4096 float4
        int k = idx >> 5, nv = idx & 31;
        float4 v = Wv[idx];
        uint32_t h0, l0, h1, l1, h2, l2, h3, l3;
        tf32_split(v.x, h0, l0); tf32_split(v.y, h1, l1);
        tf32_split(v.z, h2, l2); tf32_split(v.w, h3, l3);
        float4 hv = make_float4(__uint_as_float(h0), __uint_as_float(h1),
                                __uint_as_float(h2), __uint_as_float(h3));
        float4 lv = make_float4(__uint_as_float(l0), __uint_as_float(l1),
                                __uint_as_float(l2), __uint_as_float(l3));
        *(float4*)&Whi[k * 136 + nv * 4] = hv;
        *(float4*)&Wlo[k * 136 + nv * 4] = lv;
    }
    // load X tile (raw fp32); layer 0: X row = ztab[z[row]]
    const int* zsel = g_aIsBatch ? zb : za;
    #pragma unroll
    for (int i = 0; i < 16; ++i) {
        int idx = tid + i * 256;
        int m = idx >> 5, kv = idx & 31;
        int r = row0 + m;
        float4 v = make_float4(0.f, 0.f, 0.f, 0.f);
        if (r < NN) {
            const float4* src = useEmbed ? ((const float4*)ztab + (size_t)zsel[r] * 32)
                                         : ((const float4*)X + (size_t)r * 32);
            v = src[kv];
        }
        *(float4*)&Xs[m * 132 + kv * 4] = v;
    }
    __syncthreads();

    int wid = tid >> 5, lane = tid & 31;
    int m0 = (wid & 3) * 32;          // 0,32,64,96
    int n0 = (wid >> 2) * 64;         // 0,64
    int g  = lane >> 2;               // 0..7
    int q  = lane & 3;                // 0..3

    float acc[2][8][4];
    #pragma unroll
    for (int mt = 0; mt < 2; ++mt)
        #pragma unroll
        for (int nt = 0; nt < 8; ++nt)
            #pragma unroll
            for (int j = 0; j < 4; ++j) acc[mt][nt][j] = 0.f;

    #pragma unroll 2
    for (int ks = 0; ks < 16; ++ks) {
        int kb = ks * 8;
        uint32_t ah[2][4], al[2][4];
        #pragma unroll
        for (int mt = 0; mt < 2; ++mt) {
            int rb = m0 + mt * 16 + g;
            tf32_split(Xs[rb * 132 + kb + q],           ah[mt][0], al[mt][0]);
            tf32_split(Xs[(rb + 8) * 132 + kb + q],     ah[mt][1], al[mt][1]);
            tf32_split(Xs[rb * 132 + kb + q + 4],       ah[mt][2], al[mt][2]);
            tf32_split(Xs[(rb + 8) * 132 + kb + q + 4], ah[mt][3], al[mt][3]);
        }
        #pragma unroll
        for (int nt = 0; nt < 8; ++nt) {
            int nc = n0 + nt * 8 + g;
            uint32_t bh0 = __float_as_uint(Whi[(kb + q) * 136 + nc]);
            uint32_t bl0 = __float_as_uint(Wlo[(kb + q) * 136 + nc]);
            uint32_t bh1 = __float_as_uint(Whi[(kb + q + 4) * 136 + nc]);
            uint32_t bl1 = __float_as_uint(Wlo[(kb + q + 4) * 136 + nc]);
            #pragma unroll
            for (int mt = 0; mt < 2; ++mt) {
                asm volatile(
                    "mma.sync.aligned.m16n8k8.row.col.f32.tf32.tf32.f32 "
                    "{%0,%1,%2,%3},{%4,%5,%6,%7},{%8,%9},{%0,%1,%2,%3};\n"
                    : "+f"(acc[mt][nt][0]), "+f"(acc[mt][nt][1]),
                      "+f"(acc[mt][nt][2]), "+f"(acc[mt][nt][3])
                    : "r"(ah[mt][0]), "r"(ah[mt][1]), "r"(ah[mt][2]), "r"(ah[mt][3]),
                      "r"(bl0), "r"(bl1));
                asm volatile(
                    "mma.sync.aligned.m16n8k8.row.col.f32.tf32.tf32.f32 "
                    "{%0,%1,%2,%3},{%4,%5,%6,%7},{%8,%9},{%0,%1,%2,%3};\n"
                    : "+f"(acc[mt][nt][0]), "+f"(acc[mt][nt][1]),
                      "+f"(acc[mt][nt][2]), "+f"(acc[mt][nt][3])
                    : "r"(al[mt][0]), "r"(al[mt][1]), "r"(al[mt][2]), "r"(al[mt][3]),
                      "r"(bh0), "r"(bh1));
                asm volatile(
                    "mma.sync.aligned.m16n8k8.row.col.f32.tf32.tf32.f32 "
                    "{%0,%1,%2,%3},{%4,%5,%6,%7},{%8,%9},{%0,%1,%2,%3};\n"
                    : "+f"(acc[mt][nt][0]), "+f"(acc[mt][nt][1]),
                      "+f"(acc[mt][nt][2]), "+f"(acc[mt][nt][3])
                    : "r"(ah[mt][0]), "r"(ah[mt][1]), "r"(ah[mt][2]), "r"(ah[mt][3]),
                      "r"(bh0), "r"(bh1));
            }
        }
    }

    // store: c0,c1 -> (row, 2q),(row, 2q+1); c2,c3 -> row+8
    #pragma unroll
    for (int mt = 0; mt < 2; ++mt) {
        int r = row0 + m0 + mt * 16 + g;
        #pragma unroll
        for (int nt = 0; nt < 8; ++nt) {
            int cc = n0 + nt * 8 + 2 * q;
            if (r < NN)
                *(float2*)&Y[r * 128 + cc] = make_float2(acc[mt][nt][0], acc[mt][nt][1]);
            if (r + 8 < NN)
                *(float2*)&Y[(r + 8) * 128 + cc] = make_float2(acc[mt][nt][2], acc[mt][nt][3]);
        }
    }
}

// ---------------- CSR gather-aggregate + bias (+ReLU) fused ----------------
// one warp per node, one float4 per lane; 2-deep rotating software pipeline (R5 form)
__global__ void k_gather(const float* __restrict__ xw, const float* __restrict__ bias,
                         float* __restrict__ out, int do_relu) {
    int gtid = blockIdx.x * blockDim.x + threadIdx.x;
    int v = gtid >> 5;
    int lane = gtid & 31;
    if (v >= NN) return;

    const float4* xwv = (const float4*)xw;
    float di = g_deg[v];                 // holds dinv
    float s = di * di;                   // self-loop norm
    float4 acc = xwv[(size_t)v * 32 + lane];
    acc.x *= s; acc.y *= s; acc.z *= s; acc.w *= s;

    int p = g_rowptr[v], end = g_rowptr[v + 1];
    if (p < end) {
        int2 pr = g_epack[p];
        for (++p; p < end; ++p) {
            int2 nxt = g_epack[p];
            float nm = __int_as_float(pr.y);
            float4 xv = xwv[(size_t)pr.x * 32 + lane];
            acc.x += nm * xv.x; acc.y += nm * xv.y;
            acc.z += nm * xv.z; acc.w += nm * xv.w;
            pr = nxt;
        }
        float nm = __int_as_float(pr.y);
        float4 xv = xwv[(size_t)pr.x * 32 + lane];
        acc.x += nm * xv.x; acc.y += nm * xv.y;
        acc.z += nm * xv.z; acc.w += nm * xv.w;
    }

    float4 b = ((const float4*)bias)[lane];
    acc.x += b.x; acc.y += b.y; acc.z += b.z; acc.w += b.w;
    if (do_relu) {
        acc.x = fmaxf(acc.x, 0.f); acc.y = fmaxf(acc.y, 0.f);
        acc.z = fmaxf(acc.z, 0.f); acc.w = fmaxf(acc.w, 0.f);
    }
    ((float4*)out)[(size_t)v * 32 + lane] = acc;
}

// ---------------- readout ----------------
__global__ void k_readout(const float* __restrict__ X,
                          const int* __restrict__ cand_a, const int* __restrict__ cand_b,
                          const float* __restrict__ W1, const float* __restrict__ b1,
                          const float* __restrict__ W2, const float* __restrict__ b2,
                          float* __restrict__ out) {
    const int* batch = g_aIsBatch ? cand_a : cand_b;
    __shared__ float h[128];
    __shared__ int sc;
    __shared__ float red[4];
    int g = blockIdx.x, j = threadIdx.x;
    if (j == 0) {   // searchsorted: first idx with batch[idx] >= g
        int lo = 0, hi = NN;
        while (lo < hi) { int mid = (lo + hi) >> 1; if (batch[mid] < g) lo = mid + 1; else hi = mid; }
        sc = lo;
    }
    __syncthreads();
    int c = sc;
    h[j] = X[c * 128 + j] * X[(c + 1) * 128 + j];
    __syncthreads();
    float acc = b1[j];
    #pragma unroll 8
    for (int k = 0; k < 128; ++k) acc += h[k] * W1[k * 128 + j];
    acc = fmaxf(acc, 0.f);
    float v = acc * W2[j];
    #pragma unroll
    for (int o = 16; o; o >>= 1) v += __shfl_xor_sync(0xffffffffu, v, o);
    if ((j & 31) == 0) red[j >> 5] = v;
    __syncthreads();
    if (j == 0) out[g] = red[0] + red[1] + red[2] + red[3] + b2[0];
}

// ---------------- launch: bind inputs BY SIZE (metadata order is unknown) ----------------
extern "C" void kernel_launch(void* const* d_in, const int* in_sizes, int n_in,
                              void* d_out, int out_size) {
    const int* i100k[2] = {0, 0}; int n100k = 0;
    const void* v16k[4] = {0, 0, 0, 0}; int n16k = 0;
    const void* v128[8] = {0, 0, 0, 0, 0, 0, 0, 0}; int n128 = 0;
    const int*   ei = 0; const float* ew = 0; const float* ztab = 0;
    const float* packedW = 0; const float* packedB = 0; const float* lin2b = 0;

    for (int i = 0; i < n_in; ++i) {
        int s = in_sizes[i];
        if      (s == 2 * EE)      ei   = (const int*)d_in[i];
        else if (s == EE)          ew   = (const float*)d_in[i];
        else if (s == 1000 * HH)   ztab = (const float*)d_in[i];
        else if (s == NN)          { if (n100k < 2) i100k[n100k++] = (const int*)d_in[i]; }
        else if (s == HH * HH)     { if (n16k < 4) v16k[n16k++] = d_in[i]; }
        else if (s == 3 * HH * HH) packedW = (const float*)d_in[i];
        else if (s == HH)          { if (n128 < 8) v128[n128++] = d_in[i]; }
        else if (s == 3 * HH)      packedB = (const float*)d_in[i];
        else if (s == 1)           lin2b = (const float*)d_in[i];
    }

    const float* convW[3]; const float* convB[3];
    const float* lin1W; const float* lin1b; const float* lin2W;
    if (packedW) {
        convW[0] = packedW; convW[1] = packedW + HH * HH; convW[2] = packedW + 2 * HH * HH;
        lin1W = (const float*)v16k[0];
    } else {
        convW[0] = (const float*)v16k[0]; convW[1] = (const float*)v16k[1];
        convW[2] = (const float*)v16k[2]; lin1W = (const float*)v16k[3];
    }
    if (packedB) {
        convB[0] = packedB; convB[1] = packedB + HH; convB[2] = packedB + 2 * HH;
        lin1b = (const float*)v128[0]; lin2W = (const float*)v128[1];
    } else {
        convB[0] = (const float*)v128[0]; convB[1] = (const float*)v128[1];
        convB[2] = (const float*)v128[2];
        lin1b = (const float*)v128[3]; lin2W = (const float*)v128[4];
    }
    float* out = (float*)d_out;

    float *A, *B;
    cudaGetSymbolAddress((void**)&A, g_bufA);
    cudaGetSymbolAddress((void**)&B, g_bufB);

    const int SMEM = (128 * 132 + 2 * 128 * 136) * 4;  // 206848
    cudaFuncSetAttribute(k_gemm, cudaFuncAttributeMaxDynamicSharedMemorySize, SMEM);

    const int TB = 256;
    int nblk_n  = (NN + TB - 1) / TB;         // 391
    int nblk_e  = (EE + TB - 1) / TB;         // 6250
    int nblk_nh = (NN * 32 + TB - 1) / TB;    // 12500
    int scan_blocks = (NN + 1023) / 1024;     // 98
    int gemm_blocks = (NN + 127) / 128;       // 782

    // launches 0..2
    k_detect<<<1, 512>>>(i100k[0]);
    k_init <<<nblk_n, TB>>>();
    k_count<<<nblk_e, TB>>>(ei, ew);

    // launch 3: layer-0 GEMM (embedding fused; independent of CSR) — lands in the
    // profiler's capture window so we finally get a real GEMM profile.
    k_gemm<<<gemm_blocks, TB, SMEM>>>(A, convW[0], B, i100k[0], i100k[1], ztab, 1);

    // CSR build
    k_scan1<<<scan_blocks, 1024>>>();         // also computes dinv
    k_scan2<<<1, 128>>>(scan_blocks);
    k_scan3<<<nblk_n, TB>>>();
    k_fill <<<nblk_e, TB>>>(ei, ew);

    // layer 0 aggregate, then layers 1,2
    k_gather<<<nblk_nh, TB>>>(B, convB[0], A, 1);
    for (int l = 1; l < 3; ++l) {
        k_gemm  <<<gemm_blocks, TB, SMEM>>>(A, convW[l], B,
                                            i100k[0], i100k[1], ztab, 0);
        k_gather<<<nblk_nh, TB>>>(B, convB[l], A, (l < 2) ? 1 : 0);
    }

    // readout
    k_readout<<<GG, 128>>>(A, i100k[0], i100k[1], lin1W, lin1b, lin2W, lin2b, out);
}

// round 9
// speedup vs baseline: 1.1716x; 1.1716x over previous
#include <cuda_runtime.h>
#include <cuda_bf16.h>
#include <cstdint>

#define NN 100000
#define EE 1600000
#define HH 128
#define GG 500

// ---------------- scratch (static __device__ globals; no allocation) ----------------
__device__ float g_bufA[NN * HH];     // ping
__device__ float g_bufB[NN * HH];     // pong (xw)
__device__ float g_deg[NN];           // deg -> dinv (in place)
__device__ int   g_cnt[NN];           // histogram / fill counter
__device__ int   g_rowptr[NN + 1];
__device__ int2  g_epack[EE];         // {row, norm-bits} per CSR-ordered edge
__device__ int   g_part[128];         // scan partials (98 used)
__device__ int   g_aIsBatch;          // input-disambiguation flag

// ---------------- z/batch detector ----------------
__global__ void k_detect(const int* __restrict__ a) {
    int i = threadIdx.x;                       // 512 threads
    int v  = a[i];
    int vp = (i > 0) ? a[i - 1] : 0;
    int ok = (v >= 0) && (v < GG) && (v >= vp);
    int all = __syncthreads_and(ok);
    if (i == 0) g_aIsBatch = all;
}

// ---------------- degree ----------------
__global__ void k_init() {
    int i = blockIdx.x * blockDim.x + threadIdx.x;
    if (i < NN) { g_deg[i] = 1.0f; g_cnt[i] = 0; }   // self-loop weight 1
}

__global__ void k_count(const int* __restrict__ ei, const float* __restrict__ w) {
    int e = blockIdx.x * blockDim.x + threadIdx.x;
    if (e < EE) {
        int c = ei[EE + e];
        atomicAdd(&g_deg[c], w[e]);
        atomicAdd(&g_cnt[c], 1);
    }
}

// ---------------- CSR build (scan1 also computes dinv in place) ----------------
__global__ void k_scan1() {   // blocks of 1024 over g_cnt
    __shared__ int s[1024];
    int tid = threadIdx.x;
    int i = blockIdx.x * 1024 + tid;
    if (i < NN) { float d = g_deg[i]; g_deg[i] = (d > 0.f) ? rsqrtf(d) : 0.f; }
    int v = (i < NN) ? g_cnt[i] : 0;
    s[tid] = v; __syncthreads();
    #pragma unroll
    for (int off = 1; off < 1024; off <<= 1) {
        int t = (tid >= off) ? s[tid - off] : 0;
        __syncthreads();
        s[tid] += t; __syncthreads();
    }
    if (i < NN) g_rowptr[i] = s[tid] - v;         // exclusive within block
    if (tid == 1023) g_part[blockIdx.x] = s[1023];
}

__global__ void k_scan2(int nblocks) {   // one 128-thread block, parallel scan
    __shared__ int s[128];
    int tid = threadIdx.x;
    int v = (tid < nblocks) ? g_part[tid] : 0;
    s[tid] = v; __syncthreads();
    #pragma unroll
    for (int off = 1; off < 128; off <<= 1) {
        int t = (tid >= off) ? s[tid - off] : 0;
        __syncthreads();
        s[tid] += t; __syncthreads();
    }
    if (tid < nblocks) g_part[tid] = s[tid] - v;  // exclusive
    if (tid == 127) g_rowptr[NN] = s[127];
}

__global__ void k_scan3() {
    int i = blockIdx.x * blockDim.x + threadIdx.x;
    if (i < NN) { g_rowptr[i] += g_part[i >> 10]; g_cnt[i] = 0; }
}

// fused: CSR fill + norm computation + epack write (one edge pass)
__global__ void k_fill(const int* __restrict__ ei, const float* __restrict__ w) {
    int e = blockIdx.x * blockDim.x + threadIdx.x;
    if (e < EE) {
        int r = ei[e];
        int c = ei[EE + e];
        float nm = g_deg[r] * w[e] * g_deg[c];    // g_deg holds dinv
        int pos = g_rowptr[c] + atomicAdd(&g_cnt[c], 1);
        g_epack[pos] = make_int2(r, __float_as_int(nm));
    }
}

// ---------------- 3xTF32 tensor-core GEMM: Y[M,128] = X[M,128] @ W[128,128] ----------------
// BM=128, 512 threads (16 warps). Warp tile m16 x n64 = 8 n8 tiles, K=128 (16 k8 steps).
// W split (hi/lo tf32) precomputed once per block into smem; X split in registers.
// Layer 0 fuses the embedding lookup: X row r = ztab[z[r]].
__device__ __forceinline__ void tf32_split(float x, uint32_t& hi, uint32_t& lo) {
    asm("cvt.rna.tf32.f32 %0, %1;" : "=r"(hi) : "f"(x));
    float r = x - __uint_as_float(hi);
    asm("cvt.rna.tf32.f32 %0, %1;" : "=r"(lo) : "f"(r));
}

__global__ void __launch_bounds__(512, 1)
k_gemm(const float* __restrict__ X, const float* __restrict__ W, float* __restrict__ Y,
       const int* __restrict__ za, const int* __restrict__ zb,
       const float* __restrict__ ztab, int useEmbed) {
    extern __shared__ float sm[];
    float* Xs  = sm;                      // [128][132]
    float* Whi = sm + 128 * 132;          // [128][136]
    float* Wlo = Whi + 128 * 136;         // [128][136]
    int tid = threadIdx.x;
    int row0 = blockIdx.x * 128;

    // load W, split into hi/lo tf32 (vector stores); 4096 float4 over 512 threads
    const float4* Wv = (const float4*)W;
    #pragma unroll
    for (int i = 0; i < 8; ++i) {
        int idx = tid + i * 512;
        int k = idx >> 5, nv = idx & 31;
        float4 v = Wv[idx];
        uint32_t h0, l0, h1, l1, h2, l2, h3, l3;
        tf32_split(v.x, h0, l0); tf32_split(v.y, h1, l1);
        tf32_split(v.z, h2, l2); tf32_split(v.w, h3, l3);
        float4 hv = make_float4(__uint_as_float(h0), __uint_as_float(h1),
                                __uint_as_float(h2), __uint_as_float(h3));
        float4 lv = make_float4(__uint_as_float(l0), __uint_as_float(l1),
                                __uint_as_float(l2), __uint_as_float(l3));
        *(float4*)&Whi[k * 136 + nv * 4] = hv;
        *(float4*)&Wlo[k * 136 + nv * 4] = lv;
    }
    // load X tile (raw fp32); layer 0: X row = ztab[z[row]]
    const int* zsel = g_aIsBatch ? zb : za;
    #pragma unroll
    for (int i = 0; i < 8; ++i) {
        int idx = tid + i * 512;
        int m = idx >> 5, kv = idx & 31;
        int r = row0 + m;
        float4 v = make_float4(0.f, 0.f, 0.f, 0.f);
        if (r < NN) {
            const float4* src = useEmbed ? ((const float4*)ztab + (size_t)zsel[r] * 32)
                                         : ((const float4*)X + (size_t)r * 32);
            v = src[kv];
        }
        *(float4*)&Xs[m * 132 + kv * 4] = v;
    }
    __syncthreads();

    int wid = tid >> 5, lane = tid & 31;
    int m0 = (wid & 7) * 16;          // 0..112 (m16 tile)
    int n0 = (wid >> 3) * 64;         // 0,64
    int g  = lane >> 2;               // 0..7
    int q  = lane & 3;                // 0..3

    float acc[8][4];
    #pragma unroll
    for (int nt = 0; nt < 8; ++nt)
        #pragma unroll
        for (int j = 0; j < 4; ++j) acc[nt][j] = 0.f;

    #pragma unroll 2
    for (int ks = 0; ks < 16; ++ks) {
        int kb = ks * 8;
        uint32_t ah[4], al[4];
        int rb = m0 + g;
        tf32_split(Xs[rb * 132 + kb + q],           ah[0], al[0]);
        tf32_split(Xs[(rb + 8) * 132 + kb + q],     ah[1], al[1]);
        tf32_split(Xs[rb * 132 + kb + q + 4],       ah[2], al[2]);
        tf32_split(Xs[(rb + 8) * 132 + kb + q + 4], ah[3], al[3]);
        #pragma unroll
        for (int nt = 0; nt < 8; ++nt) {
            int nc = n0 + nt * 8 + g;
            uint32_t bh0 = __float_as_uint(Whi[(kb + q) * 136 + nc]);
            uint32_t bl0 = __float_as_uint(Wlo[(kb + q) * 136 + nc]);
            uint32_t bh1 = __float_as_uint(Whi[(kb + q + 4) * 136 + nc]);
            uint32_t bl1 = __float_as_uint(Wlo[(kb + q + 4) * 136 + nc]);
            asm volatile(
                "mma.sync.aligned.m16n8k8.row.col.f32.tf32.tf32.f32 "
                "{%0,%1,%2,%3},{%4,%5,%6,%7},{%8,%9},{%0,%1,%2,%3};\n"
                : "+f"(acc[nt][0]), "+f"(acc[nt][1]), "+f"(acc[nt][2]), "+f"(acc[nt][3])
                : "r"(ah[0]), "r"(ah[1]), "r"(ah[2]), "r"(ah[3]), "r"(bl0), "r"(bl1));
            asm volatile(
                "mma.sync.aligned.m16n8k8.row.col.f32.tf32.tf32.f32 "
                "{%0,%1,%2,%3},{%4,%5,%6,%7},{%8,%9},{%0,%1,%2,%3};\n"
                : "+f"(acc[nt][0]), "+f"(acc[nt][1]), "+f"(acc[nt][2]), "+f"(acc[nt][3])
                : "r"(al[0]), "r"(al[1]), "r"(al[2]), "r"(al[3]), "r"(bh0), "r"(bh1));
            asm volatile(
                "mma.sync.aligned.m16n8k8.row.col.f32.tf32.tf32.f32 "
                "{%0,%1,%2,%3},{%4,%5,%6,%7},{%8,%9},{%0,%1,%2,%3};\n"
                : "+f"(acc[nt][0]), "+f"(acc[nt][1]), "+f"(acc[nt][2]), "+f"(acc[nt][3])
                : "r"(ah[0]), "r"(ah[1]), "r"(ah[2]), "r"(ah[3]), "r"(bh0), "r"(bh1));
        }
    }

    // store: c0,c1 -> (row, 2q),(row, 2q+1); c2,c3 -> row+8
    {
        int r = row0 + m0 + g;
        #pragma unroll
        for (int nt = 0; nt < 8; ++nt) {
            int cc = n0 + nt * 8 + 2 * q;
            if (r < NN)
                *(float2*)&Y[r * 128 + cc] = make_float2(acc[nt][0], acc[nt][1]);
            if (r + 8 < NN)
                *(float2*)&Y[(r + 8) * 128 + cc] = make_float2(acc[nt][2], acc[nt][3]);
        }
    }
}

// ---------------- CSR gather-aggregate + bias (+ReLU) fused ----------------
// one warp per node, one float4 per lane; 2-deep rotating software pipeline
__global__ void k_gather(const float* __restrict__ xw, const float* __restrict__ bias,
                         float* __restrict__ out, int do_relu) {
    int gtid = blockIdx.x * blockDim.x + threadIdx.x;
    int v = gtid >> 5;
    int lane = gtid & 31;
    if (v >= NN) return;

    const float4* xwv = (const float4*)xw;
    float di = g_deg[v];                 // holds dinv
    float s = di * di;                   // self-loop norm
    float4 acc = xwv[(size_t)v * 32 + lane];
    acc.x *= s; acc.y *= s; acc.z *= s; acc.w *= s;

    int p = g_rowptr[v], end = g_rowptr[v + 1];
    if (p < end) {
        int2 pr = g_epack[p];
        for (++p; p < end; ++p) {
            int2 nxt = g_epack[p];
            float nm = __int_as_float(pr.y);
            float4 xv = xwv[(size_t)pr.x * 32 + lane];
            acc.x += nm * xv.x; acc.y += nm * xv.y;
            acc.z += nm * xv.z; acc.w += nm * xv.w;
            pr = nxt;
        }
        float nm = __int_as_float(pr.y);
        float4 xv = xwv[(size_t)pr.x * 32 + lane];
        acc.x += nm * xv.x; acc.y += nm * xv.y;
        acc.z += nm * xv.z; acc.w += nm * xv.w;
    }

    float4 b = ((const float4*)bias)[lane];
    acc.x += b.x; acc.y += b.y; acc.z += b.z; acc.w += b.w;
    if (do_relu) {
        acc.x = fmaxf(acc.x, 0.f); acc.y = fmaxf(acc.y, 0.f);
        acc.z = fmaxf(acc.z, 0.f); acc.w = fmaxf(acc.w, 0.f);
    }
    ((float4*)out)[(size_t)v * 32 + lane] = acc;
}

// ---------------- readout ----------------
__global__ void k_readout(const float* __restrict__ X,
                          const int* __restrict__ cand_a, const int* __restrict__ cand_b,
                          const float* __restrict__ W1, const float* __restrict__ b1,
                          const float* __restrict__ W2, const float* __restrict__ b2,
                          float* __restrict__ out) {
    const int* batch = g_aIsBatch ? cand_a : cand_b;
    __shared__ float h[128];
    __shared__ int sc;
    __shared__ float red[4];
    int g = blockIdx.x, j = threadIdx.x;
    if (j == 0) {   // searchsorted: first idx with batch[idx] >= g
        int lo = 0, hi = NN;
        while (lo < hi) { int mid = (lo + hi) >> 1; if (batch[mid] < g) lo = mid + 1; else hi = mid; }
        sc = lo;
    }
    __syncthreads();
    int c = sc;
    h[j] = X[c * 128 + j] * X[(c + 1) * 128 + j];
    __syncthreads();
    float acc = b1[j];
    #pragma unroll 8
    for (int k = 0; k < 128; ++k) acc += h[k] * W1[k * 128 + j];
    acc = fmaxf(acc, 0.f);
    float v = acc * W2[j];
    #pragma unroll
    for (int o = 16; o; o >>= 1) v += __shfl_xor_sync(0xffffffffu, v, o);
    if ((j & 31) == 0) red[j >> 5] = v;
    __syncthreads();
    if (j == 0) out[g] = red[0] + red[1] + red[2] + red[3] + b2[0];
}

// ---------------- launch: bind inputs BY SIZE (metadata order is unknown) ----------------
extern "C" void kernel_launch(void* const* d_in, const int* in_sizes, int n_in,
                              void* d_out, int out_size) {
    const int* i100k[2] = {0, 0}; int n100k = 0;
    const void* v16k[4] = {0, 0, 0, 0}; int n16k = 0;
    const void* v128[8] = {0, 0, 0, 0, 0, 0, 0, 0}; int n128 = 0;
    const int*   ei = 0; const float* ew = 0; const float* ztab = 0;
    const float* packedW = 0; const float* packedB = 0; const float* lin2b = 0;

    for (int i = 0; i < n_in; ++i) {
        int s = in_sizes[i];
        if      (s == 2 * EE)      ei   = (const int*)d_in[i];
        else if (s == EE)          ew   = (const float*)d_in[i];
        else if (s == 1000 * HH)   ztab = (const float*)d_in[i];
        else if (s == NN)          { if (n100k < 2) i100k[n100k++] = (const int*)d_in[i]; }
        else if (s == HH * HH)     { if (n16k < 4) v16k[n16k++] = d_in[i]; }
        else if (s == 3 * HH * HH) packedW = (const float*)d_in[i];
        else if (s == HH)          { if (n128 < 8) v128[n128++] = d_in[i]; }
        else if (s == 3 * HH)      packedB = (const float*)d_in[i];
        else if (s == 1)           lin2b = (const float*)d_in[i];
    }

    const float* convW[3]; const float* convB[3];
    const float* lin1W; const float* lin1b; const float* lin2W;
    if (packedW) {
        convW[0] = packedW; convW[1] = packedW + HH * HH; convW[2] = packedW + 2 * HH * HH;
        lin1W = (const float*)v16k[0];
    } else {
        convW[0] = (const float*)v16k[0]; convW[1] = (const float*)v16k[1];
        convW[2] = (const float*)v16k[2]; lin1W = (const float*)v16k[3];
    }
    if (packedB) {
        convB[0] = packedB; convB[1] = packedB + HH; convB[2] = packedB + 2 * HH;
        lin1b = (const float*)v128[0]; lin2W = (const float*)v128[1];
    } else {
        convB[0] = (const float*)v128[0]; convB[1] = (const float*)v128[1];
        convB[2] = (const float*)v128[2];
        lin1b = (const float*)v128[3]; lin2W = (const float*)v128[4];
    }
    float* out = (float*)d_out;

    float *A, *B;
    cudaGetSymbolAddress((void**)&A, g_bufA);
    cudaGetSymbolAddress((void**)&B, g_bufB);

    const int SMEM = (128 * 132 + 2 * 128 * 136) * 4;  // 206848
    cudaFuncSetAttribute(k_gemm, cudaFuncAttributeMaxDynamicSharedMemorySize, SMEM);

    const int TB = 256;
    int nblk_n  = (NN + TB - 1) / TB;         // 391
    int nblk_e  = (EE + TB - 1) / TB;         // 6250
    int nblk_nh = (NN * 32 + TB - 1) / TB;    // 12500
    int scan_blocks = (NN + 1023) / 1024;     // 98
    int gemm_blocks = (NN + 127) / 128;       // 782

    // launches 0..2
    k_detect<<<1, 512>>>(i100k[0]);
    k_init <<<nblk_n, TB>>>();
    k_count<<<nblk_e, TB>>>(ei, ew);

    // launch 3: layer-0 GEMM (embedding fused; independent of CSR) — lands in the
    // profiler's capture window so we keep getting a real GEMM profile.
    k_gemm<<<gemm_blocks, 512, SMEM>>>(A, convW[0], B, i100k[0], i100k[1], ztab, 1);

    // CSR build
    k_scan1<<<scan_blocks, 1024>>>();         // also computes dinv
    k_scan2<<<1, 128>>>(scan_blocks);
    k_scan3<<<nblk_n, TB>>>();
    k_fill <<<nblk_e, TB>>>(ei, ew);

    // layer 0 aggregate, then layers 1,2
    k_gather<<<nblk_nh, TB>>>(B, convB[0], A, 1);
    for (int l = 1; l < 3; ++l) {
        k_gemm  <<<gemm_blocks, 512, SMEM>>>(A, convW[l], B,
                                             i100k[0], i100k[1], ztab, 0);
        k_gather<<<nblk_nh, TB>>>(B, convB[l], A, (l < 2) ? 1 : 0);
    }

    // readout
    k_readout<<<GG, 128>>>(A, i100k[0], i100k[1], lin1W, lin1b, lin2W, lin2b, out);
}